// round 12
// baseline (speedup 1.0000x reference)
#include <cuda_runtime.h>
#include <cstdint>

// CrossNet collapsed form (exact algebra):
//   out = c3 * x0 + D, with c recurrence from t_l = x0 . w_l and constants
//   e1 = B0.w1, e2 = (B0+B1).w2, D = B0+B1+B2 (computed per-block in staging).
//
// f32x2 packed FMAs (fma.rn.f32x2 — PTX-only, ptxas never auto-fuses)
// halve the FMA issue count in the hot loop; plain stores.

#define CN_DIM 1024
#define CN_ORDER 3
#define CN_ROWS_PER_BLOCK 8
#define CN_THREADS 256
#define CN_WARPS (CN_THREADS / 32)
#define CN_VEC (CN_DIM / 4)        // 256 float4 per row
#define CN_V_PER_LANE 8            // 256 / 32 lanes

// 16-byte vector viewed as two packed f32x2 halves (register pairs).
struct __align__(16) P2 { unsigned long long a, b; };

__device__ __forceinline__ unsigned long long fma2(unsigned long long x,
                                                   unsigned long long y,
                                                   unsigned long long z)
{
    unsigned long long d;
    asm("fma.rn.f32x2 %0, %1, %2, %3;" : "=l"(d) : "l"(x), "l"(y), "l"(z));
    return d;
}

__device__ __forceinline__ unsigned long long pack2(float lo, float hi)
{
    unsigned long long r;
    asm("mov.b64 %0, {%1, %2};" : "=l"(r) : "f"(lo), "f"(hi));
    return r;
}

__device__ __forceinline__ float sum2(unsigned long long v)
{
    float lo, hi;
    asm("mov.b64 {%0, %1}, %2;" : "=f"(lo), "=f"(hi) : "l"(v));
    return lo + hi;
}

__global__ __launch_bounds__(CN_THREADS, 4)
void crossnet_fused_kernel(const float* __restrict__ x0,
                           const float* __restrict__ W,
                           const float* __restrict__ B,
                           float* __restrict__ out,
                           int batch)
{
    __shared__ float sW[CN_ORDER * CN_DIM];
    __shared__ float sD[CN_DIM];
    __shared__ float sE[2];
    __shared__ float red1[CN_WARPS];
    __shared__ float red2[CN_WARPS];

    const int tid  = threadIdx.x;
    const int warp = tid >> 5;
    const int lane = tid & 31;
    const int row  = blockIdx.x * CN_ROWS_PER_BLOCK + warp;
    const bool active = (row < batch);

    // Fire this warp's x0 row loads FIRST (8 independent LDG.128/lane),
    // overlapping the staging + barrier below.
    const P2* __restrict__ xrow =
        (const P2*)(x0 + (size_t)(active ? row : 0) * CN_DIM);
    P2 x[CN_V_PER_LANE];
    #pragma unroll
    for (int i = 0; i < CN_V_PER_LANE; i++)
        x[i] = xrow[i * 32 + lane];

    // ---- staging: W -> smem; compute D, e1, e2 from B/W (L2-hit reads) ----
    {
        const int i = tid;  // CN_VEC == CN_THREADS: one float4 per thread
        const float4* gW = (const float4*)W;
        float4 w0 = gW[i];
        float4 w1 = gW[CN_VEC + i];
        float4 w2 = gW[2 * CN_VEC + i];
        ((float4*)sW)[i]              = w0;
        ((float4*)sW)[CN_VEC + i]     = w1;
        ((float4*)sW)[2 * CN_VEC + i] = w2;

        const float4* gB = (const float4*)B;
        float4 b0 = gB[i];
        float4 b1 = gB[CN_VEC + i];
        float4 b2 = gB[2 * CN_VEC + i];

        // e1 = B0 . w1
        float p1 = 0.f;
        p1 = fmaf(b0.x, w1.x, p1); p1 = fmaf(b0.y, w1.y, p1);
        p1 = fmaf(b0.z, w1.z, p1); p1 = fmaf(b0.w, w1.w, p1);
        // d2 = B0 + B1 ; e2 = d2 . w2
        float4 d2 = make_float4(b0.x + b1.x, b0.y + b1.y, b0.z + b1.z, b0.w + b1.w);
        float p2 = 0.f;
        p2 = fmaf(d2.x, w2.x, p2); p2 = fmaf(d2.y, w2.y, p2);
        p2 = fmaf(d2.z, w2.z, p2); p2 = fmaf(d2.w, w2.w, p2);
        // D = d2 + B2
        ((float4*)sD)[i] = make_float4(d2.x + b2.x, d2.y + b2.y,
                                       d2.z + b2.z, d2.w + b2.w);

        #pragma unroll
        for (int off = 16; off > 0; off >>= 1) {
            p1 += __shfl_xor_sync(0xffffffffu, p1, off);
            p2 += __shfl_xor_sync(0xffffffffu, p2, off);
        }
        if (lane == 0) { red1[warp] = p1; red2[warp] = p2; }
    }
    __syncthreads();
    if (tid == 0) {
        float e1 = 0.f, e2 = 0.f;
        #pragma unroll
        for (int w = 0; w < CN_WARPS; w++) { e1 += red1[w]; e2 += red2[w]; }
        sE[0] = e1; sE[1] = e2;
    }
    __syncthreads();
    if (!active) return;

    const float e1 = sE[0], e2 = sE[1];
    const P2* w0 = (const P2*)(sW + 0 * CN_DIM);
    const P2* w1 = (const P2*)(sW + 1 * CN_DIM);
    const P2* w2 = (const P2*)(sW + 2 * CN_DIM);

    // three dots t_l = x0 . w_l, packed f32x2: 2 independent chains per dot
    unsigned long long s0a = 0ull, s0b = 0ull;
    unsigned long long s1a = 0ull, s1b = 0ull;
    unsigned long long s2a = 0ull, s2b = 0ull;
    #pragma unroll
    for (int i = 0; i < CN_V_PER_LANE; i++) {
        P2 xv = x[i];
        P2 wv;
        wv = w0[i * 32 + lane];
        s0a = fma2(xv.a, wv.a, s0a);
        s0b = fma2(xv.b, wv.b, s0b);
        wv = w1[i * 32 + lane];
        s1a = fma2(xv.a, wv.a, s1a);
        s1b = fma2(xv.b, wv.b, s1b);
        wv = w2[i * 32 + lane];
        s2a = fma2(xv.a, wv.a, s2a);
        s2b = fma2(xv.b, wv.b, s2b);
    }
    float t0 = sum2(s0a) + sum2(s0b);
    float t1 = sum2(s1a) + sum2(s1b);
    float t2 = sum2(s2a) + sum2(s2b);

    // warp reductions (independent, interleaved)
    #pragma unroll
    for (int off = 16; off > 0; off >>= 1) {
        t0 += __shfl_xor_sync(0xffffffffu, t0, off);
        t1 += __shfl_xor_sync(0xffffffffu, t1, off);
        t2 += __shfl_xor_sync(0xffffffffu, t2, off);
    }

    // scalar recurrence
    float c = 1.0f + t0;              // c1
    c = fmaf(c, t1, c) + e1;          // c2
    c = fmaf(c, t2, c) + e2;          // c3

    // out = c * x0 + D, packed
    const unsigned long long cpk = pack2(c, c);
    const P2* dv = (const P2*)sD;
    P2* __restrict__ orow = (P2*)(out + (size_t)row * CN_DIM);
    #pragma unroll
    for (int i = 0; i < CN_V_PER_LANE; i++) {
        P2 d = dv[i * 32 + lane];
        P2 o;
        o.a = fma2(cpk, x[i].a, d.a);
        o.b = fma2(cpk, x[i].b, d.b);
        orow[i * 32 + lane] = o;
    }
}

extern "C" void kernel_launch(void* const* d_in, const int* in_sizes, int n_in,
                              void* d_out, int out_size)
{
    const float* x0 = (const float*)d_in[0];
    const float* W  = (const float*)d_in[1];
    const float* B  = (const float*)d_in[2];
    float* out      = (float*)d_out;

    const int batch = in_sizes[0] / CN_DIM;
    const int grid  = (batch + CN_ROWS_PER_BLOCK - 1) / CN_ROWS_PER_BLOCK;

    crossnet_fused_kernel<<<grid, CN_THREADS>>>(x0, W, B, out, batch);
}